// round 7
// baseline (speedup 1.0000x reference)
#include <cuda_runtime.h>
#include <math.h>

#define Hh 64
#define Ww 64
#define MAXB 8
#define MAXP 512
#define MAXF 512
#define RECF 32
#define NCHUNK 8
#define FPCmax 64
#define NTILE 32
#define EPSd 1e-10f
#define KEXP 142.85714285714286f   // MULT*MULT/DELTA
#define EXPANDc 0.02f
#define NPIX (Hh * Ww)

// scratch (device globals; no allocation allowed)
__device__ float  g_face[MAXB * MAXF * RECF];      // face records
__device__ float4 g_partA[MAXB * NCHUNK * NPIX];   // bestz, bw0, bw1, bestfid
__device__ float  g_partP[MAXB * NCHUNK * NPIX];   // prod
__device__ int    g_cnt[MAXB * NTILE];             // per (b,tile) arrival counter

// ---------------- Kernel 1: per-face geometry, one thread per face ----------------
__global__ void __launch_bounds__(128)
geom_kernel(const float* __restrict__ verts,
            const int* __restrict__ faces,
            const float* __restrict__ rot,
            const float* __restrict__ pos,
            const float* __restrict__ proj,
            float* __restrict__ out_normal1,
            int B, int P, int F)
{
    int idx = blockIdx.x * blockDim.x + threadIdx.x;
    if (idx >= B * F) return;
    int b = idx / F;

    float R0 = rot[b*9+0], R1 = rot[b*9+1], R2 = rot[b*9+2];
    float R3 = rot[b*9+3], R4 = rot[b*9+4], R5 = rot[b*9+5];
    float R6 = rot[b*9+6], R7 = rot[b*9+7], R8 = rot[b*9+8];
    float p0 = pos[b*3+0], p1 = pos[b*3+1], p2 = pos[b*3+2];
    float pr0 = proj[0], pr1 = proj[1], pr2 = proj[2];

    const int* fi = faces + (size_t)idx * 3;
    int idxs[3] = {fi[0], fi[1], fi[2]};
    float pcx[3], pcy[3], pcz[3], X[3], Y[3];
    #pragma unroll
    for (int k = 0; k < 3; ++k) {
        const float* v = verts + ((size_t)(b * P + idxs[k])) * 3;
        float d0 = v[0]-p0, d1 = v[1]-p1, d2 = v[2]-p2;
        pcx[k] = R0*d0 + R1*d1 + R2*d2;
        pcy[k] = R3*d0 + R4*d1 + R5*d2;
        pcz[k] = R6*d0 + R7*d1 + R8*d2;
        float zz = pcz[k] * pr2;
        X[k] = (pcx[k] * pr0) / zz;
        Y[k] = (pcy[k] * pr1) / zz;
    }
    float e1x = pcx[1]-pcx[0], e1y = pcy[1]-pcy[0], e1z = pcz[1]-pcz[0];
    float e2x = pcx[2]-pcx[0], e2y = pcy[2]-pcy[0], e2z = pcz[2]-pcz[0];
    float nx = e1y*e2z - e1z*e2y;
    float ny = e1z*e2x - e1x*e2z;
    float nz = e1x*e2y - e1y*e2x;
    float nrm = sqrtf(nx*nx + ny*ny + nz*nz) + 1e-12f;
    float* on = out_normal1 + (size_t)idx * 3;
    on[0] = nx / nrm; on[1] = ny / nrm; on[2] = nz / nrm;

    float ax = X[0], ay = Y[0], bx = X[1], by = Y[1], cx = X[2], cy = Y[2];
    float z0 = pcz[0], z1 = pcz[1], z2s = pcz[2];

    float det = (by - cy)*(ax - cx) + (cx - bx)*(ay - cy);
    float adet = fabsf(det);
    float det_safe = (adet < EPSd) ? EPSd : det;
    float inv = 1.0f / det_safe;
    bool valid = (nz > 0.0f) && (adet > EPSd);

    float a0 = (by - cy) * inv, b0 = (cx - bx) * inv;
    float c0 = -(a0 * cx + b0 * cy);
    float a1 = (cy - ay) * inv, b1 = (ax - cx) * inv;
    float c1 = -(a1 * cx + b1 * cy);

    float xmin = fminf(fminf(ax, bx), cx) - EXPANDc;
    float xmax = fmaxf(fmaxf(ax, bx), cx) + EXPANDc;
    float ymin = fminf(fminf(ay, by), cy) - EXPANDc;
    float ymax = fmaxf(fmaxf(ay, by), cy) + EXPANDc;

    float* Rr = g_face + (size_t)idx * RECF;
    float4* R4p = (float4*)Rr;
    float v0x = bx - ax, v0y = by - ay;
    float v1x = cx - bx, v1y = cy - by;
    float v2x = ax - cx, v2y = ay - cy;
    R4p[0] = make_float4(xmin, xmax, ymin, ymax);
    R4p[1] = make_float4(a0, b0, c0, valid ? (z0 - z2s) : 0.0f);
    R4p[2] = make_float4(a1, b1, c1, valid ? (z1 - z2s) : 0.0f);
    R4p[3] = make_float4(valid ? z2s : -1e10f, valid ? (float)(idx % F) : -1.0f, ax, ay);
    R4p[4] = make_float4(v0x, v0y, 1.0f / (v0x*v0x + v0y*v0y + 1e-12f), bx);
    R4p[5] = make_float4(by, v1x, v1y, 1.0f / (v1x*v1x + v1y*v1y + 1e-12f));
    R4p[6] = make_float4(cx, cy, v2x, v2y);
    R4p[7] = make_float4(1.0f / (v2x*v2x + v2y*v2y + 1e-12f), 0.0f, 0.0f, 0.0f);
}

// ---------------- Kernel 2: pixel loop + fused combine ----------------
__global__ void __launch_bounds__(128)
render_kernel(const int* __restrict__ faces,
              const float* __restrict__ colors,
              float* __restrict__ out,
              int B, int P, int F,
              int offP, int offH)
{
    __shared__ float sface[FPCmax * RECF];   // 8 KB
    __shared__ int wcnt[4];
    __shared__ int sh_old;

    int b = blockIdx.z, chunk = blockIdx.y, tile = blockIdx.x;
    int FPC = F / NCHUNK;
    int tid = threadIdx.x;
    int lane = tid & 31, wid = tid >> 5;
    int tx = tile & 3, ty = tile >> 2;      // 4 x-tiles (16px), 8 y-tiles (8px)

    float txlo = (2.0f * (float)(tx*16)      + 1.0f - (float)Ww) / (float)Ww;
    float txhi = (2.0f * (float)(tx*16 + 15) + 1.0f - (float)Ww) / (float)Ww;
    float tyhi = ((float)Hh - 2.0f * (float)(ty*8)      - 1.0f) / (float)Hh;
    float tylo = ((float)Hh - 2.0f * (float)(ty*8 + 7)  - 1.0f) / (float)Hh;

    // ---- cull against precomputed bboxes ----
    bool acc = false;
    int fg = 0;
    const float4* src = nullptr;
    if (tid < FPC) {
        fg = chunk * FPC + tid;
        src = (const float4*)(g_face + ((size_t)(b * F + fg)) * RECF);
        float4 bb = __ldg((const float4*)src);
        acc = (bb.x <= txhi) && (bb.y >= txlo) && (bb.z <= tyhi) && (bb.w >= tylo);
    }

    unsigned m = __ballot_sync(0xffffffffu, acc);
    if (lane == 0) wcnt[wid] = __popc(m);
    __syncthreads();
    int base = 0, nf = 0;
    #pragma unroll
    for (int w = 0; w < 4; ++w) {
        int c = wcnt[w];
        if (w < wid) base += c;
        nf += c;
    }
    if (acc) {
        int slot = base + __popc(m & ((1u << lane) - 1u));
        float4* dst = (float4*)(sface + slot * RECF);
        #pragma unroll
        for (int k = 0; k < 8; ++k) dst[k] = __ldg(src + k);
    }
    __syncthreads();

    // ---- pixel mapping: 16x8 tile, 4 warps of 8x4, 1 pixel/thread ----
    int lx = lane & 7, ly = lane >> 3;
    int wx = wid & 1, wy = wid >> 1;
    int x = tx * 16 + wx * 8 + lx;
    int y = ty * 8  + wy * 4 + ly;

    float px = (2.0f * (float)x + 1.0f - (float)Ww) / (float)Ww;
    float py = ((float)Hh - 2.0f * (float)y - 1.0f) / (float)Hh;

    float prod = 1.0f;
    float bestz = -1e30f;
    float bw0 = 0.0f, bw1 = 0.0f, bf = -1.0f;

    float4 bb = (nf > 0) ? *(const float4*)(&sface[0]) : make_float4(0,0,0,0);
    for (int f = 0; f < nf; ++f) {
        float4 bbn;
        if (f + 1 < nf) bbn = *(const float4*)(&sface[(f + 1) * RECF]);
        const float* Rr = &sface[f * RECF];
        bool inb = (px >= bb.x) && (px <= bb.y) && (py >= bb.z) && (py <= bb.w);
        if (__ballot_sync(0xffffffffu, inb) != 0u) {
            float4 e0 = *(const float4*)(Rr + 4);
            float4 e1 = *(const float4*)(Rr + 8);
            float w0 = fmaf(e0.x, px, fmaf(e0.y, py, e0.z));
            float w1 = fmaf(e1.x, px, fmaf(e1.y, py, e1.z));
            float w2 = 1.0f - w0 - w1;
            bool covered = (w0 >= 0.0f) && (w1 >= 0.0f) && (w2 >= 0.0f);
            float4 zf = *(const float4*)(Rr + 12);   // zc, fid, ax, ay

            if (inb) {
                if (covered) {
                    float z = zf.x + w0 * e0.w + w1 * e1.w;
                    if (z > bestz) { bestz = z; bw0 = w0; bw1 = w1; bf = zf.y; }
                    prod = 0.0f;
                } else {
                    float4 s0 = *(const float4*)(Rr + 16);
                    float4 s1 = *(const float4*)(Rr + 20);
                    float4 s2 = *(const float4*)(Rr + 24);
                    float inv2 = Rr[28];

                    float rx = px - zf.z, ry = py - zf.w;
                    float t0 = fminf(fmaxf((rx * s0.x + ry * s0.y) * s0.z, 0.0f), 1.0f);
                    float ex = rx - t0 * s0.x, ey = ry - t0 * s0.y;
                    float d2 = ex * ex + ey * ey;

                    rx = px - s0.w; ry = py - s1.x;
                    float t1 = fminf(fmaxf((rx * s1.y + ry * s1.z) * s1.w, 0.0f), 1.0f);
                    ex = rx - t1 * s1.y; ey = ry - t1 * s1.z;
                    d2 = fminf(d2, ex * ex + ey * ey);

                    rx = px - s2.x; ry = py - s2.y;
                    float t2 = fminf(fmaxf((rx * s2.z + ry * s2.w) * inv2, 0.0f), 1.0f);
                    ex = rx - t2 * s2.z; ey = ry - t2 * s2.w;
                    d2 = fminf(d2, ex * ex + ey * ey);

                    prod *= (1.0f - __expf(-d2 * KEXP));
                }
            }
        }
        bb = bbn;
    }

    int pix = y * Ww + x;
    int o = (b * NCHUNK + chunk) * NPIX + pix;
    __stcg(&g_partA[o], make_float4(bestz, bw0, bw1, bf));
    __stcg(&g_partP[o], prod);

    // ---- last CTA per (b,tile) combines ----
    __threadfence();
    __syncthreads();
    if (tid == 0) sh_old = atomicAdd(&g_cnt[b * NTILE + tile], 1);
    __syncthreads();
    if (sh_old != NCHUNK - 1) return;
    __threadfence();

    float Z = -1e38f, b0c = 0.0f, b1c = 0.0f, bff = -1.0f;
    float pacc = 1.0f;
    #pragma unroll
    for (int c = 0; c < NCHUNK; ++c) {
        int oo = (b * NCHUNK + c) * NPIX + pix;
        float4 a = __ldcg(&g_partA[oo]);
        pacc *= __ldcg(&g_partP[oo]);
        if (a.x > Z) { Z = a.x; b0c = a.y; b1c = a.z; bff = a.w; }
    }

    float r = 0.0f, g = 0.0f, bl = 0.0f, hm = 0.0f;
    if (bff >= 0.0f) {
        int fid = (int)bff;
        const int* fi = faces + ((size_t)(b * F + fid)) * 3;
        const float* cA = colors + ((size_t)(b * P + fi[0])) * 3;
        const float* cB = colors + ((size_t)(b * P + fi[1])) * 3;
        const float* cC = colors + ((size_t)(b * P + fi[2])) * 3;
        float w2 = 1.0f - b0c - b1c;
        r  = b0c * cA[0] + b1c * cB[0] + w2 * cC[0];
        g  = b0c * cA[1] + b1c * cB[1] + w2 * cC[1];
        bl = b0c * cA[2] + b1c * cB[2] + w2 * cC[2];
        hm = b0c + b1c + w2;
    }

    int gidx = b * NPIX + pix;
    float* rgb = out + (size_t)gidx * 3;
    rgb[0] = r; rgb[1] = g; rgb[2] = bl;
    out[offP + gidx] = 1.0f - pacc;
    out[offH + gidx] = hm;

    if (tid == 0) atomicExch(&g_cnt[b * NTILE + tile], 0);
}

extern "C" void kernel_launch(void* const* d_in, const int* in_sizes, int n_in,
                              void* d_out, int out_size)
{
    const float* verts  = (const float*)d_in[0];
    const int*   faces  = (const int*)d_in[1];
    const float* rot    = (const float*)d_in[2];
    const float* pos    = (const float*)d_in[3];
    const float* proj   = (const float*)d_in[4];
    const float* colors = (const float*)d_in[5];
    float* out = (float*)d_out;

    int B = in_sizes[3] / 3;
    int P = in_sizes[0] / (3 * B);
    int F = in_sizes[1] / (3 * B);

    int offP = B * NPIX * 3;        // improb
    int offN = offP + B * NPIX;     // normal1
    int offH = offN + B * F * 3;    // hardmask

    int nf = B * F;
    geom_kernel<<<(nf + 127) / 128, 128>>>(verts, faces, rot, pos, proj,
                                           out + offN, B, P, F);

    dim3 grid(NTILE, NCHUNK, B);
    render_kernel<<<grid, 128>>>(faces, colors, out, B, P, F, offP, offH);
}

// round 8
// speedup vs baseline: 1.2000x; 1.2000x over previous
#include <cuda_runtime.h>
#include <math.h>

#define Hh 64
#define Ww 64
#define MAXB 8
#define MAXP 512
#define MAXF 512
#define RECF 32
#define NCHUNK 8
#define FPCmax 64
#define NTILE 32
#define EPSd 1e-10f
#define KEXP 142.85714285714286f   // MULT*MULT/DELTA
#define EXPANDc 0.02f
#define NPIX (Hh * Ww)

// scratch (device globals; no allocation allowed)
__device__ float4 g_partA[MAXB * NCHUNK * NPIX];   // bestz, bw0, bw1, bestfid(as float)
__device__ float  g_partP[MAXB * NCHUNK * NPIX];   // prod
__device__ int    g_cnt[MAXB * NTILE];             // per (b,tile) arrival counter

__global__ void __launch_bounds__(128)
render_kernel(const float* __restrict__ verts,
              const int* __restrict__ faces,
              const float* __restrict__ rot,
              const float* __restrict__ pos,
              const float* __restrict__ proj,
              const float* __restrict__ colors,
              float* __restrict__ out,
              int B, int P, int F,
              int offP, int offN, int offH)
{
    __shared__ float sface[FPCmax * RECF];   // 8 KB
    __shared__ int wcnt[4];
    __shared__ int sh_old;

    int b = blockIdx.z, chunk = blockIdx.y, tile = blockIdx.x;
    int FPC = F / NCHUNK;
    int tid = threadIdx.x;
    int lane = tid & 31, wid = tid >> 5;
    int tx = tile & 3, ty = tile >> 2;      // 4 x-tiles (16px), 8 y-tiles (8px)

    // NDC extents of this 16x8 pixel tile
    float txlo = (2.0f * (float)(tx*16)      + 1.0f - (float)Ww) / (float)Ww;
    float txhi = (2.0f * (float)(tx*16 + 15) + 1.0f - (float)Ww) / (float)Ww;
    float tyhi = ((float)Hh - 2.0f * (float)(ty*8)      - 1.0f) / (float)Hh;
    float tylo = ((float)Hh - 2.0f * (float)(ty*8 + 7)  - 1.0f) / (float)Hh;

    // ---- per-face geometry (threads 0..FPC-1), direct vertex transform ----
    bool acc = false;
    int fg = 0;
    float ax=0, ay=0, bx=0, by=0, cx=0, cy=0;
    float z0=0, z1=0, z2s=0, nz=0;
    float xmin=0, xmax=0, ymin=0, ymax=0;

    if (tid < FPC) {
        float R0 = rot[b*9+0], R1 = rot[b*9+1], R2 = rot[b*9+2];
        float R3 = rot[b*9+3], R4 = rot[b*9+4], R5 = rot[b*9+5];
        float R6 = rot[b*9+6], R7 = rot[b*9+7], R8 = rot[b*9+8];
        float p0 = pos[b*3+0], p1 = pos[b*3+1], p2 = pos[b*3+2];
        float pr0 = proj[0], pr1 = proj[1], pr2 = proj[2];

        fg = chunk * FPC + tid;
        const int* fi = faces + ((size_t)(b * F + fg)) * 3;
        int idxs[3] = {fi[0], fi[1], fi[2]};
        float pcx[3], pcy[3], pcz[3], X[3], Y[3];
        #pragma unroll
        for (int k = 0; k < 3; ++k) {
            const float* v = verts + ((size_t)(b * P + idxs[k])) * 3;
            float d0 = v[0]-p0, d1 = v[1]-p1, d2 = v[2]-p2;
            pcx[k] = R0*d0 + R1*d1 + R2*d2;
            pcy[k] = R3*d0 + R4*d1 + R5*d2;
            pcz[k] = R6*d0 + R7*d1 + R8*d2;
            float zz = pcz[k] * pr2;
            X[k] = (pcx[k] * pr0) / zz;
            Y[k] = (pcy[k] * pr1) / zz;
        }
        float e1x = pcx[1]-pcx[0], e1y = pcy[1]-pcy[0], e1z = pcz[1]-pcz[0];
        float e2x = pcx[2]-pcx[0], e2y = pcy[2]-pcy[0], e2z = pcz[2]-pcz[0];
        float nx = e1y*e2z - e1z*e2y;
        float ny = e1z*e2x - e1x*e2z;
        nz = e1x*e2y - e1y*e2x;
        if (tile == 0) {
            float nrm = sqrtf(nx*nx + ny*ny + nz*nz) + 1e-12f;
            float* on = out + offN + ((size_t)(b * F + fg)) * 3;
            on[0] = nx / nrm; on[1] = ny / nrm; on[2] = nz / nrm;
        }
        ax = X[0]; ay = Y[0]; bx = X[1]; by = Y[1]; cx = X[2]; cy = Y[2];
        z0 = pcz[0]; z1 = pcz[1]; z2s = pcz[2];

        xmin = fminf(fminf(ax, bx), cx) - EXPANDc;
        xmax = fmaxf(fmaxf(ax, bx), cx) + EXPANDc;
        ymin = fminf(fminf(ay, by), cy) - EXPANDc;
        ymax = fmaxf(fmaxf(ay, by), cy) + EXPANDc;
        acc = (xmin <= txhi) && (xmax >= txlo) && (ymin <= tyhi) && (ymax >= tylo);
    }

    // ---- order-preserving compaction ----
    unsigned m = __ballot_sync(0xffffffffu, acc);
    if (lane == 0) wcnt[wid] = __popc(m);
    __syncthreads();
    int base = 0, nf = 0;
    #pragma unroll
    for (int w = 0; w < 4; ++w) {
        int c = wcnt[w];
        if (w < wid) base += c;
        nf += c;
    }

    if (acc) {
        int slot = base + __popc(m & ((1u << lane) - 1u));
        float* Rr = sface + slot * RECF;

        float det = (by - cy)*(ax - cx) + (cx - bx)*(ay - cy);
        float adet = fabsf(det);
        float det_safe = (adet < EPSd) ? EPSd : det;
        float inv = 1.0f / det_safe;
        bool valid = (nz > 0.0f) && (adet > EPSd);

        float a0 = (by - cy) * inv, b0 = (cx - bx) * inv;
        float c0 = -(a0 * cx + b0 * cy);
        float a1 = (cy - ay) * inv, b1 = (ax - cx) * inv;
        float c1 = -(a1 * cx + b1 * cy);

        Rr[0] = xmin; Rr[1] = xmax; Rr[2] = ymin; Rr[3] = ymax;
        Rr[4] = a0; Rr[5] = b0; Rr[6] = c0; Rr[7] = valid ? (z0 - z2s) : 0.0f;
        Rr[8] = a1; Rr[9] = b1; Rr[10] = c1; Rr[11] = valid ? (z1 - z2s) : 0.0f;
        Rr[12] = valid ? z2s : -1e10f;
        Rr[13] = valid ? (float)fg : -1.0f;
        Rr[14] = ax; Rr[15] = ay;
        float v0x = bx - ax, v0y = by - ay;
        Rr[16] = v0x; Rr[17] = v0y;
        Rr[18] = 1.0f / (v0x*v0x + v0y*v0y + 1e-12f);
        Rr[19] = bx;
        Rr[20] = by;
        float v1x = cx - bx, v1y = cy - by;
        Rr[21] = v1x; Rr[22] = v1y;
        Rr[23] = 1.0f / (v1x*v1x + v1y*v1y + 1e-12f);
        Rr[24] = cx; Rr[25] = cy;
        float v2x = ax - cx, v2y = ay - cy;
        Rr[26] = v2x; Rr[27] = v2y;
        Rr[28] = 1.0f / (v2x*v2x + v2y*v2y + 1e-12f);
    }
    __syncthreads();

    // ---- pixel mapping: 16x8 tile, 4 warps of 8x4, 1 pixel/thread ----
    int lx = lane & 7, ly = lane >> 3;
    int wx = wid & 1, wy = wid >> 1;
    int x = tx * 16 + wx * 8 + lx;
    int y = ty * 8  + wy * 4 + ly;

    float px = (2.0f * (float)x + 1.0f - (float)Ww) / (float)Ww;
    float py = ((float)Hh - 2.0f * (float)y - 1.0f) / (float)Hh;

    float prod = 1.0f;
    float bestz = -1e30f;
    float bw0 = 0.0f, bw1 = 0.0f, bf = -1.0f;

    float4 bb = (nf > 0) ? *(const float4*)(&sface[0]) : make_float4(0,0,0,0);
    for (int f = 0; f < nf; ++f) {
        float4 bbn;
        if (f + 1 < nf) bbn = *(const float4*)(&sface[(f + 1) * RECF]);
        const float* Rr = &sface[f * RECF];
        bool inb = (px >= bb.x) && (px <= bb.y) && (py >= bb.z) && (py <= bb.w);
        if (__ballot_sync(0xffffffffu, inb) != 0u) {
            float4 e0 = *(const float4*)(Rr + 4);
            float4 e1 = *(const float4*)(Rr + 8);
            float4 zf = *(const float4*)(Rr + 12);   // zc, fid, ax, ay
            float4 s0 = *(const float4*)(Rr + 16);   // v0x,v0y,inv0,bx
            float4 s1 = *(const float4*)(Rr + 20);   // by,v1x,v1y,inv1
            float4 s2 = *(const float4*)(Rr + 24);   // cx,cy,v2x,v2y
            float inv2 = Rr[28];

            // barycentrics + depth (always)
            float w0 = fmaf(e0.x, px, fmaf(e0.y, py, e0.z));
            float w1 = fmaf(e1.x, px, fmaf(e1.y, py, e1.z));
            float w2 = 1.0f - w0 - w1;
            bool covered = (w0 >= 0.0f) && (w1 >= 0.0f) && (w2 >= 0.0f);
            float z = fmaf(w0, e0.w, fmaf(w1, e1.w, zf.x));

            bool upd = inb && covered && (z > bestz);
            bestz = upd ? z : bestz;
            bw0 = upd ? w0 : bw0;
            bw1 = upd ? w1 : bw1;
            bf  = upd ? zf.y : bf;

            // segment distances (always; select out below)
            float rx = px - zf.z, ry = py - zf.w;
            float t0 = fminf(fmaxf((rx * s0.x + ry * s0.y) * s0.z, 0.0f), 1.0f);
            float ex = fmaf(-t0, s0.x, rx), ey = fmaf(-t0, s0.y, ry);
            float d2 = ex * ex + ey * ey;

            rx = px - s0.w; ry = py - s1.x;
            float t1 = fminf(fmaxf((rx * s1.y + ry * s1.z) * s1.w, 0.0f), 1.0f);
            ex = fmaf(-t1, s1.y, rx); ey = fmaf(-t1, s1.z, ry);
            d2 = fminf(d2, ex * ex + ey * ey);

            rx = px - s2.x; ry = py - s2.y;
            float t2 = fminf(fmaxf((rx * s2.z + ry * s2.w) * inv2, 0.0f), 1.0f);
            ex = fmaf(-t2, s2.z, rx); ey = fmaf(-t2, s2.w, ry);
            d2 = fminf(d2, ex * ex + ey * ey);

            float factor = covered ? 0.0f : (1.0f - __expf(-d2 * KEXP));
            factor = inb ? factor : 1.0f;
            prod *= factor;
        }
        bb = bbn;
    }

    int pix = y * Ww + x;
    int o = (b * NCHUNK + chunk) * NPIX + pix;
    __stcg(&g_partA[o], make_float4(bestz, bw0, bw1, bf));
    __stcg(&g_partP[o], prod);

    // ---- last CTA per (b,tile) combines ----
    __threadfence();
    __syncthreads();
    if (tid == 0) sh_old = atomicAdd(&g_cnt[b * NTILE + tile], 1);
    __syncthreads();
    if (sh_old != NCHUNK - 1) return;
    __threadfence();

    float Z = -1e38f, b0c = 0.0f, b1c = 0.0f, bff = -1.0f;
    float pacc = 1.0f;
    #pragma unroll
    for (int c = 0; c < NCHUNK; ++c) {
        int oo = (b * NCHUNK + c) * NPIX + pix;
        float4 a = __ldcg(&g_partA[oo]);
        pacc *= __ldcg(&g_partP[oo]);
        bool u = (a.x > Z);
        Z = u ? a.x : Z; b0c = u ? a.y : b0c; b1c = u ? a.z : b1c; bff = u ? a.w : bff;
    }

    float r = 0.0f, g = 0.0f, bl = 0.0f, hm = 0.0f;
    if (bff >= 0.0f) {
        int fid = (int)bff;
        const int* fi = faces + ((size_t)(b * F + fid)) * 3;
        const float* cA = colors + ((size_t)(b * P + fi[0])) * 3;
        const float* cB = colors + ((size_t)(b * P + fi[1])) * 3;
        const float* cC = colors + ((size_t)(b * P + fi[2])) * 3;
        float w2 = 1.0f - b0c - b1c;
        r  = b0c * cA[0] + b1c * cB[0] + w2 * cC[0];
        g  = b0c * cA[1] + b1c * cB[1] + w2 * cC[1];
        bl = b0c * cA[2] + b1c * cB[2] + w2 * cC[2];
        hm = b0c + b1c + w2;
    }

    int gidx = b * NPIX + pix;
    float* rgb = out + (size_t)gidx * 3;
    rgb[0] = r; rgb[1] = g; rgb[2] = bl;
    out[offP + gidx] = 1.0f - pacc;
    out[offH + gidx] = hm;

    if (tid == 0) atomicExch(&g_cnt[b * NTILE + tile], 0);   // reset for next replay
}

extern "C" void kernel_launch(void* const* d_in, const int* in_sizes, int n_in,
                              void* d_out, int out_size)
{
    const float* verts  = (const float*)d_in[0];
    const int*   faces  = (const int*)d_in[1];
    const float* rot    = (const float*)d_in[2];
    const float* pos    = (const float*)d_in[3];
    const float* proj   = (const float*)d_in[4];
    const float* colors = (const float*)d_in[5];
    float* out = (float*)d_out;

    int B = in_sizes[3] / 3;
    int P = in_sizes[0] / (3 * B);
    int F = in_sizes[1] / (3 * B);

    int offP = B * NPIX * 3;        // improb
    int offN = offP + B * NPIX;     // normal1
    int offH = offN + B * F * 3;    // hardmask

    dim3 grid(NTILE, NCHUNK, B);
    render_kernel<<<grid, 128>>>(verts, faces, rot, pos, proj, colors, out,
                                 B, P, F, offP, offN, offH);
}

// round 9
// speedup vs baseline: 1.2280x; 1.0234x over previous
#include <cuda_runtime.h>
#include <math.h>

#define Hh 64
#define Ww 64
#define MAXB 8
#define MAXP 512
#define MAXF 512
#define RECF 32
#define NCHUNK 16
#define FPCmax 32
#define NTILE 32
#define EPSd 1e-10f
#define KEXP 142.85714285714286f   // MULT*MULT/DELTA
#define EXPANDc 0.02f
#define NPIX (Hh * Ww)

// scratch (device globals; no allocation allowed)
__device__ float4 g_partA[MAXB * NCHUNK * NPIX];   // bestz, bw0, bw1, bestfid(as float)
__device__ float  g_partP[MAXB * NCHUNK * NPIX];   // prod
__device__ int    g_cnt[MAXB * NTILE];             // per (b,tile) arrival counter

__global__ void __launch_bounds__(128, 12)
render_kernel(const float* __restrict__ verts,
              const int* __restrict__ faces,
              const float* __restrict__ rot,
              const float* __restrict__ pos,
              const float* __restrict__ proj,
              const float* __restrict__ colors,
              float* __restrict__ out,
              int B, int P, int F,
              int offP, int offN, int offH)
{
    __shared__ float sface[FPCmax * RECF];   // 4 KB
    __shared__ int wcnt[4];
    __shared__ int sh_old;

    int b = blockIdx.z, chunk = blockIdx.y, tile = blockIdx.x;
    int FPC = F / NCHUNK;                    // 32
    int tid = threadIdx.x;
    int lane = tid & 31, wid = tid >> 5;
    int tx = tile & 3, ty = tile >> 2;       // 4 x-tiles (16px), 8 y-tiles (8px)

    // NDC extents of this 16x8 pixel tile
    float txlo = (2.0f * (float)(tx*16)      + 1.0f - (float)Ww) / (float)Ww;
    float txhi = (2.0f * (float)(tx*16 + 15) + 1.0f - (float)Ww) / (float)Ww;
    float tyhi = ((float)Hh - 2.0f * (float)(ty*8)      - 1.0f) / (float)Hh;
    float tylo = ((float)Hh - 2.0f * (float)(ty*8 + 7)  - 1.0f) / (float)Hh;

    // ---- per-face geometry (threads 0..FPC-1), direct vertex transform ----
    bool acc = false;
    int fg = 0;
    float ax=0, ay=0, bx=0, by=0, cx=0, cy=0;
    float z0=0, z1=0, z2s=0, nz=0;
    float xmin=0, xmax=0, ymin=0, ymax=0;

    if (tid < FPC) {
        float R0 = rot[b*9+0], R1 = rot[b*9+1], R2 = rot[b*9+2];
        float R3 = rot[b*9+3], R4 = rot[b*9+4], R5 = rot[b*9+5];
        float R6 = rot[b*9+6], R7 = rot[b*9+7], R8 = rot[b*9+8];
        float p0 = pos[b*3+0], p1 = pos[b*3+1], p2 = pos[b*3+2];
        float pr0 = proj[0], pr1 = proj[1], pr2 = proj[2];

        fg = chunk * FPC + tid;
        const int* fi = faces + ((size_t)(b * F + fg)) * 3;
        int idxs[3] = {fi[0], fi[1], fi[2]};
        float pcx[3], pcy[3], pcz[3], X[3], Y[3];
        #pragma unroll
        for (int k = 0; k < 3; ++k) {
            const float* v = verts + ((size_t)(b * P + idxs[k])) * 3;
            float d0 = v[0]-p0, d1 = v[1]-p1, d2 = v[2]-p2;
            pcx[k] = R0*d0 + R1*d1 + R2*d2;
            pcy[k] = R3*d0 + R4*d1 + R5*d2;
            pcz[k] = R6*d0 + R7*d1 + R8*d2;
            float zz = pcz[k] * pr2;
            X[k] = (pcx[k] * pr0) / zz;
            Y[k] = (pcy[k] * pr1) / zz;
        }
        float e1x = pcx[1]-pcx[0], e1y = pcy[1]-pcy[0], e1z = pcz[1]-pcz[0];
        float e2x = pcx[2]-pcx[0], e2y = pcy[2]-pcy[0], e2z = pcz[2]-pcz[0];
        float nx = e1y*e2z - e1z*e2y;
        float ny = e1z*e2x - e1x*e2z;
        nz = e1x*e2y - e1y*e2x;
        if (tile == 0) {
            float nrm = sqrtf(nx*nx + ny*ny + nz*nz) + 1e-12f;
            float* on = out + offN + ((size_t)(b * F + fg)) * 3;
            on[0] = nx / nrm; on[1] = ny / nrm; on[2] = nz / nrm;
        }
        ax = X[0]; ay = Y[0]; bx = X[1]; by = Y[1]; cx = X[2]; cy = Y[2];
        z0 = pcz[0]; z1 = pcz[1]; z2s = pcz[2];

        xmin = fminf(fminf(ax, bx), cx) - EXPANDc;
        xmax = fmaxf(fmaxf(ax, bx), cx) + EXPANDc;
        ymin = fminf(fminf(ay, by), cy) - EXPANDc;
        ymax = fmaxf(fmaxf(ay, by), cy) + EXPANDc;
        acc = (xmin <= txhi) && (xmax >= txlo) && (ymin <= tyhi) && (ymax >= tylo);
    }

    // ---- order-preserving compaction (only warp 0 holds faces) ----
    unsigned m = __ballot_sync(0xffffffffu, acc);
    if (lane == 0) wcnt[wid] = __popc(m);
    __syncthreads();
    int nf = wcnt[0];

    if (acc) {
        int slot = __popc(m & ((1u << lane) - 1u));
        float* Rr = sface + slot * RECF;

        float det = (by - cy)*(ax - cx) + (cx - bx)*(ay - cy);
        float adet = fabsf(det);
        float det_safe = (adet < EPSd) ? EPSd : det;
        float inv = 1.0f / det_safe;
        bool valid = (nz > 0.0f) && (adet > EPSd);

        float a0 = (by - cy) * inv, b0 = (cx - bx) * inv;
        float c0 = -(a0 * cx + b0 * cy);
        float a1 = (cy - ay) * inv, b1 = (ax - cx) * inv;
        float c1 = -(a1 * cx + b1 * cy);

        Rr[0] = xmin; Rr[1] = xmax; Rr[2] = ymin; Rr[3] = ymax;
        Rr[4] = a0; Rr[5] = b0; Rr[6] = c0; Rr[7] = valid ? (z0 - z2s) : 0.0f;
        Rr[8] = a1; Rr[9] = b1; Rr[10] = c1; Rr[11] = valid ? (z1 - z2s) : 0.0f;
        Rr[12] = valid ? z2s : -1e10f;
        Rr[13] = valid ? (float)fg : -1.0f;
        Rr[14] = ax; Rr[15] = ay;
        float v0x = bx - ax, v0y = by - ay;
        Rr[16] = v0x; Rr[17] = v0y;
        Rr[18] = 1.0f / (v0x*v0x + v0y*v0y + 1e-12f);
        Rr[19] = bx;
        Rr[20] = by;
        float v1x = cx - bx, v1y = cy - by;
        Rr[21] = v1x; Rr[22] = v1y;
        Rr[23] = 1.0f / (v1x*v1x + v1y*v1y + 1e-12f);
        Rr[24] = cx; Rr[25] = cy;
        float v2x = ax - cx, v2y = ay - cy;
        Rr[26] = v2x; Rr[27] = v2y;
        Rr[28] = 1.0f / (v2x*v2x + v2y*v2y + 1e-12f);
    }
    __syncthreads();

    // ---- pixel mapping: 16x8 tile, 4 warps of 8x4, 1 pixel/thread ----
    int lx = lane & 7, ly = lane >> 3;
    int wx = wid & 1, wy = wid >> 1;
    int x = tx * 16 + wx * 8 + lx;
    int y = ty * 8  + wy * 4 + ly;

    float px = (2.0f * (float)x + 1.0f - (float)Ww) / (float)Ww;
    float py = ((float)Hh - 2.0f * (float)y - 1.0f) / (float)Hh;

    float prod = 1.0f;
    float bestz = -1e30f;
    float bw0 = 0.0f, bw1 = 0.0f, bf = -1.0f;

    float4 bb = (nf > 0) ? *(const float4*)(&sface[0]) : make_float4(0,0,0,0);
    for (int f = 0; f < nf; ++f) {
        float4 bbn;
        if (f + 1 < nf) bbn = *(const float4*)(&sface[(f + 1) * RECF]);
        const float* Rr = &sface[f * RECF];
        bool inb = (px >= bb.x) && (px <= bb.y) && (py >= bb.z) && (py <= bb.w);
        if (__ballot_sync(0xffffffffu, inb) != 0u) {
            float4 e0 = *(const float4*)(Rr + 4);
            float4 e1 = *(const float4*)(Rr + 8);
            float4 zf = *(const float4*)(Rr + 12);   // zc, fid, ax, ay
            float4 s0 = *(const float4*)(Rr + 16);   // v0x,v0y,inv0,bx
            float4 s1 = *(const float4*)(Rr + 20);   // by,v1x,v1y,inv1
            float4 s2 = *(const float4*)(Rr + 24);   // cx,cy,v2x,v2y
            float inv2 = Rr[28];

            float w0 = fmaf(e0.x, px, fmaf(e0.y, py, e0.z));
            float w1 = fmaf(e1.x, px, fmaf(e1.y, py, e1.z));
            float w2 = 1.0f - w0 - w1;
            bool covered = (w0 >= 0.0f) && (w1 >= 0.0f) && (w2 >= 0.0f);
            float z = fmaf(w0, e0.w, fmaf(w1, e1.w, zf.x));

            bool upd = inb && covered && (z > bestz);
            bestz = upd ? z : bestz;
            bw0 = upd ? w0 : bw0;
            bw1 = upd ? w1 : bw1;
            bf  = upd ? zf.y : bf;

            float rx = px - zf.z, ry = py - zf.w;
            float t0 = fminf(fmaxf((rx * s0.x + ry * s0.y) * s0.z, 0.0f), 1.0f);
            float ex = fmaf(-t0, s0.x, rx), ey = fmaf(-t0, s0.y, ry);
            float d2 = ex * ex + ey * ey;

            rx = px - s0.w; ry = py - s1.x;
            float t1 = fminf(fmaxf((rx * s1.y + ry * s1.z) * s1.w, 0.0f), 1.0f);
            ex = fmaf(-t1, s1.y, rx); ey = fmaf(-t1, s1.z, ry);
            d2 = fminf(d2, ex * ex + ey * ey);

            rx = px - s2.x; ry = py - s2.y;
            float t2 = fminf(fmaxf((rx * s2.z + ry * s2.w) * inv2, 0.0f), 1.0f);
            ex = fmaf(-t2, s2.z, rx); ey = fmaf(-t2, s2.w, ry);
            d2 = fminf(d2, ex * ex + ey * ey);

            float factor = covered ? 0.0f : (1.0f - __expf(-d2 * KEXP));
            factor = inb ? factor : 1.0f;
            prod *= factor;
        }
        bb = bbn;
    }

    int pix = y * Ww + x;
    int o = (b * NCHUNK + chunk) * NPIX + pix;
    __stcg(&g_partA[o], make_float4(bestz, bw0, bw1, bf));
    __stcg(&g_partP[o], prod);

    // ---- last CTA per (b,tile) combines ----
    __threadfence();
    __syncthreads();
    if (tid == 0) sh_old = atomicAdd(&g_cnt[b * NTILE + tile], 1);
    __syncthreads();
    if (sh_old != NCHUNK - 1) return;
    __threadfence();

    float Z = -1e38f, b0c = 0.0f, b1c = 0.0f, bff = -1.0f;
    float pacc = 1.0f;
    #pragma unroll
    for (int c = 0; c < NCHUNK; ++c) {
        int oo = (b * NCHUNK + c) * NPIX + pix;
        float4 a = __ldcg(&g_partA[oo]);
        pacc *= __ldcg(&g_partP[oo]);
        bool u = (a.x > Z);
        Z = u ? a.x : Z; b0c = u ? a.y : b0c; b1c = u ? a.z : b1c; bff = u ? a.w : bff;
    }

    float r = 0.0f, g = 0.0f, bl = 0.0f, hm = 0.0f;
    if (bff >= 0.0f) {
        int fid = (int)bff;
        const int* fi = faces + ((size_t)(b * F + fid)) * 3;
        const float* cA = colors + ((size_t)(b * P + fi[0])) * 3;
        const float* cB = colors + ((size_t)(b * P + fi[1])) * 3;
        const float* cC = colors + ((size_t)(b * P + fi[2])) * 3;
        float w2 = 1.0f - b0c - b1c;
        r  = b0c * cA[0] + b1c * cB[0] + w2 * cC[0];
        g  = b0c * cA[1] + b1c * cB[1] + w2 * cC[1];
        bl = b0c * cA[2] + b1c * cB[2] + w2 * cC[2];
        hm = b0c + b1c + w2;
    }

    int gidx = b * NPIX + pix;
    float* rgb = out + (size_t)gidx * 3;
    rgb[0] = r; rgb[1] = g; rgb[2] = bl;
    out[offP + gidx] = 1.0f - pacc;
    out[offH + gidx] = hm;

    if (tid == 0) atomicExch(&g_cnt[b * NTILE + tile], 0);   // reset for next replay
}

extern "C" void kernel_launch(void* const* d_in, const int* in_sizes, int n_in,
                              void* d_out, int out_size)
{
    const float* verts  = (const float*)d_in[0];
    const int*   faces  = (const int*)d_in[1];
    const float* rot    = (const float*)d_in[2];
    const float* pos    = (const float*)d_in[3];
    const float* proj   = (const float*)d_in[4];
    const float* colors = (const float*)d_in[5];
    float* out = (float*)d_out;

    int B = in_sizes[3] / 3;
    int P = in_sizes[0] / (3 * B);
    int F = in_sizes[1] / (3 * B);

    int offP = B * NPIX * 3;        // improb
    int offN = offP + B * NPIX;     // normal1
    int offH = offN + B * F * 3;    // hardmask

    dim3 grid(NTILE, NCHUNK, B);
    render_kernel<<<grid, 128>>>(verts, faces, rot, pos, proj, colors, out,
                                 B, P, F, offP, offN, offH);
}

// round 10
// speedup vs baseline: 1.2294x; 1.0011x over previous
#include <cuda_runtime.h>
#include <math.h>

#define Hh 64
#define Ww 64
#define MAXB 8
#define MAXP 512
#define MAXF 512
#define RECF 32
#define NCHUNK 16
#define FPCmax 32
#define NTILE 32
#define EPSd 1e-10f
#define KEXP 142.85714285714286f   // MULT*MULT/DELTA
#define EXPANDc 0.02f
#define NPIX (Hh * Ww)

// scratch (device globals; no allocation allowed)
__device__ float4 g_partA[MAXB * NCHUNK * NPIX];   // bestz, bw0, bw1, bestfid(as float)
__device__ float  g_partP[MAXB * NCHUNK * NPIX];   // prod
__device__ int    g_cnt[MAXB * NTILE];             // per (b,tile) arrival counter

__global__ void __launch_bounds__(128, 12)
render_kernel(const float* __restrict__ verts,
              const int* __restrict__ faces,
              const float* __restrict__ rot,
              const float* __restrict__ pos,
              const float* __restrict__ proj,
              const float* __restrict__ colors,
              float* __restrict__ out,
              int B, int P, int F,
              int offP, int offN, int offH)
{
    __shared__ float sface[FPCmax * RECF];   // 4 KB
    __shared__ int   swidx[4][FPCmax];       // per-warp culled face index list
    __shared__ int   wcnt0;
    __shared__ int   sh_old;

    int b = blockIdx.z, chunk = blockIdx.y, tile = blockIdx.x;
    int FPC = F / NCHUNK;                    // 32
    int tid = threadIdx.x;
    int lane = tid & 31, wid = tid >> 5;
    int tx = tile & 3, ty = tile >> 2;       // 4 x-tiles (16px), 8 y-tiles (8px)

    // NDC extents of this 16x8 pixel tile
    float txlo = (2.0f * (float)(tx*16)      + 1.0f - (float)Ww) / (float)Ww;
    float txhi = (2.0f * (float)(tx*16 + 15) + 1.0f - (float)Ww) / (float)Ww;
    float tyhi = ((float)Hh - 2.0f * (float)(ty*8)      - 1.0f) / (float)Hh;
    float tylo = ((float)Hh - 2.0f * (float)(ty*8 + 7)  - 1.0f) / (float)Hh;

    // ---- per-face geometry (threads 0..FPC-1, warp 0), direct vertex transform ----
    bool acc = false;
    int fg = 0;
    float ax=0, ay=0, bx=0, by=0, cx=0, cy=0;
    float z0=0, z1=0, z2s=0, nz=0;
    float xmin=0, xmax=0, ymin=0, ymax=0;

    if (tid < FPC) {
        float R0 = rot[b*9+0], R1 = rot[b*9+1], R2 = rot[b*9+2];
        float R3 = rot[b*9+3], R4 = rot[b*9+4], R5 = rot[b*9+5];
        float R6 = rot[b*9+6], R7 = rot[b*9+7], R8 = rot[b*9+8];
        float p0 = pos[b*3+0], p1 = pos[b*3+1], p2 = pos[b*3+2];
        float pr0 = proj[0], pr1 = proj[1], pr2 = proj[2];

        fg = chunk * FPC + tid;
        const int* fi = faces + ((size_t)(b * F + fg)) * 3;
        int idxs[3] = {fi[0], fi[1], fi[2]};
        float pcx[3], pcy[3], pcz[3], X[3], Y[3];
        #pragma unroll
        for (int k = 0; k < 3; ++k) {
            const float* v = verts + ((size_t)(b * P + idxs[k])) * 3;
            float d0 = v[0]-p0, d1 = v[1]-p1, d2 = v[2]-p2;
            pcx[k] = R0*d0 + R1*d1 + R2*d2;
            pcy[k] = R3*d0 + R4*d1 + R5*d2;
            pcz[k] = R6*d0 + R7*d1 + R8*d2;
            float zz = pcz[k] * pr2;
            X[k] = (pcx[k] * pr0) / zz;
            Y[k] = (pcy[k] * pr1) / zz;
        }
        float e1x = pcx[1]-pcx[0], e1y = pcy[1]-pcy[0], e1z = pcz[1]-pcz[0];
        float e2x = pcx[2]-pcx[0], e2y = pcy[2]-pcy[0], e2z = pcz[2]-pcz[0];
        float nx = e1y*e2z - e1z*e2y;
        float ny = e1z*e2x - e1x*e2z;
        nz = e1x*e2y - e1y*e2x;
        if (tile == 0) {
            float nrm = sqrtf(nx*nx + ny*ny + nz*nz) + 1e-12f;
            float* on = out + offN + ((size_t)(b * F + fg)) * 3;
            on[0] = nx / nrm; on[1] = ny / nrm; on[2] = nz / nrm;
        }
        ax = X[0]; ay = Y[0]; bx = X[1]; by = Y[1]; cx = X[2]; cy = Y[2];
        z0 = pcz[0]; z1 = pcz[1]; z2s = pcz[2];

        xmin = fminf(fminf(ax, bx), cx) - EXPANDc;
        xmax = fmaxf(fmaxf(ax, bx), cx) + EXPANDc;
        ymin = fminf(fminf(ay, by), cy) - EXPANDc;
        ymax = fmaxf(fmaxf(ay, by), cy) + EXPANDc;
        acc = (xmin <= txhi) && (xmax >= txlo) && (ymin <= tyhi) && (ymax >= tylo);
    }

    // ---- CTA-level order-preserving compaction (faces live in warp 0) ----
    unsigned m = __ballot_sync(0xffffffffu, acc);
    if (tid == 0) wcnt0 = __popc(m);

    if (acc) {
        int slot = __popc(m & ((1u << lane) - 1u));
        float* Rr = sface + slot * RECF;

        float det = (by - cy)*(ax - cx) + (cx - bx)*(ay - cy);
        float adet = fabsf(det);
        float det_safe = (adet < EPSd) ? EPSd : det;
        float inv = 1.0f / det_safe;
        bool valid = (nz > 0.0f) && (adet > EPSd);

        float a0 = (by - cy) * inv, b0 = (cx - bx) * inv;
        float c0 = -(a0 * cx + b0 * cy);
        float a1 = (cy - ay) * inv, b1 = (ax - cx) * inv;
        float c1 = -(a1 * cx + b1 * cy);

        Rr[0] = xmin; Rr[1] = xmax; Rr[2] = ymin; Rr[3] = ymax;
        Rr[4] = a0; Rr[5] = b0; Rr[6] = c0; Rr[7] = valid ? (z0 - z2s) : 0.0f;
        Rr[8] = a1; Rr[9] = b1; Rr[10] = c1; Rr[11] = valid ? (z1 - z2s) : 0.0f;
        Rr[12] = valid ? z2s : -1e10f;
        Rr[13] = valid ? (float)fg : -1.0f;
        Rr[14] = ax; Rr[15] = ay;
        float v0x = bx - ax, v0y = by - ay;
        Rr[16] = v0x; Rr[17] = v0y;
        Rr[18] = 1.0f / (v0x*v0x + v0y*v0y + 1e-12f);
        Rr[19] = bx;
        Rr[20] = by;
        float v1x = cx - bx, v1y = cy - by;
        Rr[21] = v1x; Rr[22] = v1y;
        Rr[23] = 1.0f / (v1x*v1x + v1y*v1y + 1e-12f);
        Rr[24] = cx; Rr[25] = cy;
        float v2x = ax - cx, v2y = ay - cy;
        Rr[26] = v2x; Rr[27] = v2y;
        Rr[28] = 1.0f / (v2x*v2x + v2y*v2y + 1e-12f);
    }
    __syncthreads();
    int nf = wcnt0;

    // ---- per-warp second-level cull into private index list ----
    int wx = wid & 1, wy = wid >> 1;            // 2x2 warps over 16x8 tile
    float wxlo = (2.0f * (float)(tx*16 + wx*8)     + 1.0f - (float)Ww) / (float)Ww;
    float wxhi = (2.0f * (float)(tx*16 + wx*8 + 7) + 1.0f - (float)Ww) / (float)Ww;
    float wyhi = ((float)Hh - 2.0f * (float)(ty*8 + wy*4)     - 1.0f) / (float)Hh;
    float wylo = ((float)Hh - 2.0f * (float)(ty*8 + wy*4 + 3) - 1.0f) / (float)Hh;

    bool wacc = false;
    if (lane < nf) {
        const float* Rb = &sface[lane * RECF];
        float fxmin = Rb[0], fxmax = Rb[1], fymin = Rb[2], fymax = Rb[3];
        wacc = (fxmin <= wxhi) && (fxmax >= wxlo) && (fymin <= wyhi) && (fymax >= wylo);
    }
    unsigned wm = __ballot_sync(0xffffffffu, wacc);
    if (wacc) {
        int ws = __popc(wm & ((1u << lane) - 1u));
        swidx[wid][ws] = lane;
    }
    int wnf = __popc(wm);
    __syncwarp();

    // ---- pixel mapping: 1 pixel/thread ----
    int lx = lane & 7, ly = lane >> 3;
    int x = tx * 16 + wx * 8 + lx;
    int y = ty * 8  + wy * 4 + ly;

    float px = (2.0f * (float)x + 1.0f - (float)Ww) / (float)Ww;
    float py = ((float)Hh - 2.0f * (float)y - 1.0f) / (float)Hh;

    float prod = 1.0f;
    float bestz = -1e30f;
    float bw0 = 0.0f, bw1 = 0.0f, bf = -1.0f;

    for (int k = 0; k < wnf; ++k) {
        const float* Rr = &sface[swidx[wid][k] * RECF];
        float4 bb = *(const float4*)(Rr + 0);
        float4 e0 = *(const float4*)(Rr + 4);
        float4 e1 = *(const float4*)(Rr + 8);
        float4 zf = *(const float4*)(Rr + 12);   // zc, fid, ax, ay

        bool inb = (px >= bb.x) && (px <= bb.y) && (py >= bb.z) && (py <= bb.w);

        float w0 = fmaf(e0.x, px, fmaf(e0.y, py, e0.z));
        float w1 = fmaf(e1.x, px, fmaf(e1.y, py, e1.z));
        float w2 = 1.0f - w0 - w1;
        bool covered = (w0 >= 0.0f) && (w1 >= 0.0f) && (w2 >= 0.0f);
        float z = fmaf(w0, e0.w, fmaf(w1, e1.w, zf.x));

        bool upd = inb && covered && (z > bestz);
        bestz = upd ? z : bestz;
        bw0 = upd ? w0 : bw0;
        bw1 = upd ? w1 : bw1;
        bf  = upd ? zf.y : bf;

        float factor;
        if (__any_sync(0xffffffffu, inb && !covered)) {
            float4 s0 = *(const float4*)(Rr + 16);   // v0x,v0y,inv0,bx
            float4 s1 = *(const float4*)(Rr + 20);   // by,v1x,v1y,inv1
            float4 s2 = *(const float4*)(Rr + 24);   // cx,cy,v2x,v2y
            float inv2 = Rr[28];

            float rx = px - zf.z, ry = py - zf.w;
            float t0 = fminf(fmaxf((rx * s0.x + ry * s0.y) * s0.z, 0.0f), 1.0f);
            float ex = fmaf(-t0, s0.x, rx), ey = fmaf(-t0, s0.y, ry);
            float d2 = ex * ex + ey * ey;

            rx = px - s0.w; ry = py - s1.x;
            float t1 = fminf(fmaxf((rx * s1.y + ry * s1.z) * s1.w, 0.0f), 1.0f);
            ex = fmaf(-t1, s1.y, rx); ey = fmaf(-t1, s1.z, ry);
            d2 = fminf(d2, ex * ex + ey * ey);

            rx = px - s2.x; ry = py - s2.y;
            float t2 = fminf(fmaxf((rx * s2.z + ry * s2.w) * inv2, 0.0f), 1.0f);
            ex = fmaf(-t2, s2.z, rx); ey = fmaf(-t2, s2.w, ry);
            d2 = fminf(d2, ex * ex + ey * ey);

            factor = covered ? 0.0f : (1.0f - __expf(-d2 * KEXP));
            factor = inb ? factor : 1.0f;
        } else {
            factor = (inb && covered) ? 0.0f : 1.0f;
        }
        prod *= factor;
    }

    int pix = y * Ww + x;
    int o = (b * NCHUNK + chunk) * NPIX + pix;
    __stcg(&g_partA[o], make_float4(bestz, bw0, bw1, bf));
    __stcg(&g_partP[o], prod);

    // ---- last CTA per (b,tile) combines ----
    __threadfence();
    __syncthreads();
    if (tid == 0) sh_old = atomicAdd(&g_cnt[b * NTILE + tile], 1);
    __syncthreads();
    if (sh_old != NCHUNK - 1) return;
    __threadfence();

    float Z = -1e38f, b0c = 0.0f, b1c = 0.0f, bff = -1.0f;
    float pacc = 1.0f;
    #pragma unroll
    for (int c = 0; c < NCHUNK; ++c) {
        int oo = (b * NCHUNK + c) * NPIX + pix;
        float4 a = __ldcg(&g_partA[oo]);
        pacc *= __ldcg(&g_partP[oo]);
        bool u = (a.x > Z);
        Z = u ? a.x : Z; b0c = u ? a.y : b0c; b1c = u ? a.z : b1c; bff = u ? a.w : bff;
    }

    float r = 0.0f, g = 0.0f, bl = 0.0f, hm = 0.0f;
    if (bff >= 0.0f) {
        int fid = (int)bff;
        const int* fi = faces + ((size_t)(b * F + fid)) * 3;
        const float* cA = colors + ((size_t)(b * P + fi[0])) * 3;
        const float* cB = colors + ((size_t)(b * P + fi[1])) * 3;
        const float* cC = colors + ((size_t)(b * P + fi[2])) * 3;
        float w2 = 1.0f - b0c - b1c;
        r  = b0c * cA[0] + b1c * cB[0] + w2 * cC[0];
        g  = b0c * cA[1] + b1c * cB[1] + w2 * cC[1];
        bl = b0c * cA[2] + b1c * cB[2] + w2 * cC[2];
        hm = b0c + b1c + w2;
    }

    int gidx = b * NPIX + pix;
    float* rgb = out + (size_t)gidx * 3;
    rgb[0] = r; rgb[1] = g; rgb[2] = bl;
    out[offP + gidx] = 1.0f - pacc;
    out[offH + gidx] = hm;

    if (tid == 0) atomicExch(&g_cnt[b * NTILE + tile], 0);   // reset for next replay
}

extern "C" void kernel_launch(void* const* d_in, const int* in_sizes, int n_in,
                              void* d_out, int out_size)
{
    const float* verts  = (const float*)d_in[0];
    const int*   faces  = (const int*)d_in[1];
    const float* rot    = (const float*)d_in[2];
    const float* pos    = (const float*)d_in[3];
    const float* proj   = (const float*)d_in[4];
    const float* colors = (const float*)d_in[5];
    float* out = (float*)d_out;

    int B = in_sizes[3] / 3;
    int P = in_sizes[0] / (3 * B);
    int F = in_sizes[1] / (3 * B);

    int offP = B * NPIX * 3;        // improb
    int offN = offP + B * NPIX;     // normal1
    int offH = offN + B * F * 3;    // hardmask

    dim3 grid(NTILE, NCHUNK, B);
    render_kernel<<<grid, 128>>>(verts, faces, rot, pos, proj, colors, out,
                                 B, P, F, offP, offN, offH);
}